// round 1
// baseline (speedup 1.0000x reference)
#include <cuda_runtime.h>

#define BB 64
#define NN 1024
#define DD 512
#define KK 64
#define FEPS 1e-12f

// ---------------- scratch (device globals; no allocation in kernel_launch) ---
__device__ float g_a[BB * NN * KK];      // softmax assignments [B,N,K]  (16.8 MB)
__device__ float g_vkd[BB * KK * DD];    // VLAD accumulator   [B,K,D]  ( 8.4 MB)
__device__ float g_asum[BB * KK];        // sum_n a[b,n,k]
__device__ float g_S[BB * KK];           // per-(b,k) sum of squares

typedef unsigned long long u64;

// ---------------- packed f32x2 helpers (sm_103a) ----------------------------
__device__ __forceinline__ u64 pack2(float lo, float hi) {
    u64 r;
    asm("mov.b64 %0, {%1, %2};" : "=l"(r) : "r"(__float_as_int(lo)), "r"(__float_as_int(hi)));
    return r;
}
__device__ __forceinline__ void unpack2(u64 v, float &lo, float &hi) {
    int a, b;
    asm("mov.b64 {%0, %1}, %2;" : "=r"(a), "=r"(b) : "l"(v));
    lo = __int_as_float(a);
    hi = __int_as_float(b);
}
__device__ __forceinline__ void ffma2(u64 &d, u64 a, u64 b) {
    asm("fma.rn.f32x2 %0, %1, %2, %0;" : "+l"(d) : "l"(a), "l"(b));
}

// ============================================================================
// Phase A: s = x @ w  (per 128-pixel tile), softmax over K=64, store a.
// grid = B*N/128 = 512 CTAs, 256 threads.
// Thread layout: tk = tid&7 (k-groups, interleaved pairs), tn = tid>>3 (pixels)
// Thread owns 4 pixels (tn, tn+32, tn+64, tn+96) x 8 k-values
// k mapping: pair j of thread tk -> k = 2*(tk + 8*j), 2*(tk+8*j)+1
// ============================================================================
__global__ __launch_bounds__(256) void phaseA(const float* __restrict__ x,
                                              const float* __restrict__ w) {
    __shared__ float xs[128][20];   // 128 pixels x 16 d, stride 20 (16B-aligned rows, no bank conflicts)
    __shared__ float ws[16][64];    // 16 d x 64 k

    const int blk = blockIdx.x;
    const int b   = blk >> 3;
    const int n0  = (blk & 7) << 7;
    const int tid = threadIdx.x;
    const int tk  = tid & 7;
    const int tn  = tid >> 3;

    u64 acc[4][4];
#pragma unroll
    for (int i = 0; i < 4; i++)
#pragma unroll
        for (int j = 0; j < 4; j++) acc[i][j] = 0ull;

    const float* xb = x + ((size_t)(b * NN + n0)) * DD;

    const int lr = tid >> 1;          // 0..127 pixel row for x staging
    const int lc = (tid & 1) << 3;    // 0 or 8
    const int wd = tid >> 4;          // 0..15 d row for w staging
    const int wk = (tid & 15) << 2;   // 0..60 step 4

    for (int dc = 0; dc < DD; dc += 16) {
        // stage x tile [128 x 16]
        float4 v0 = *reinterpret_cast<const float4*>(xb + (size_t)lr * DD + dc + lc);
        float4 v1 = *reinterpret_cast<const float4*>(xb + (size_t)lr * DD + dc + lc + 4);
        *reinterpret_cast<float4*>(&xs[lr][lc])     = v0;
        *reinterpret_cast<float4*>(&xs[lr][lc + 4]) = v1;
        // stage w tile [16 x 64]
        float4 wv4 = *reinterpret_cast<const float4*>(w + (size_t)(dc + wd) * KK + wk);
        *reinterpret_cast<float4*>(&ws[wd][wk]) = wv4;
        __syncthreads();

#pragma unroll
        for (int d = 0; d < 16; d++) {
            u64 xp[4];
#pragma unroll
            for (int i = 0; i < 4; i++) {
                float xv = xs[tn + (i << 5)][d];
                xp[i] = pack2(xv, xv);
            }
            u64 wv[4];
#pragma unroll
            for (int j = 0; j < 4; j++)
                wv[j] = *reinterpret_cast<const u64*>(&ws[d][(tk + (j << 3)) << 1]);
#pragma unroll
            for (int i = 0; i < 4; i++)
#pragma unroll
                for (int j = 0; j < 4; j++) ffma2(acc[i][j], xp[i], wv[j]);
        }
        __syncthreads();
    }

    // softmax over K=64: each pixel's 64 logits live in 8 consecutive lanes (tk 0..7)
#pragma unroll
    for (int i = 0; i < 4; i++) {
        float s[8];
#pragma unroll
        for (int j = 0; j < 4; j++) unpack2(acc[i][j], s[2 * j], s[2 * j + 1]);
        float m = s[0];
#pragma unroll
        for (int kk = 1; kk < 8; kk++) m = fmaxf(m, s[kk]);
#pragma unroll
        for (int o = 1; o < 8; o <<= 1) m = fmaxf(m, __shfl_xor_sync(0xffffffffu, m, o));
        float sum = 0.f;
#pragma unroll
        for (int kk = 0; kk < 8; kk++) { s[kk] = __expf(s[kk] - m); sum += s[kk]; }
#pragma unroll
        for (int o = 1; o < 8; o <<= 1) sum += __shfl_xor_sync(0xffffffffu, sum, o);
        const float r = 1.0f / sum;

        float* dst = g_a + ((size_t)(b * NN + n0 + tn + (i << 5))) * KK;
#pragma unroll
        for (int j = 0; j < 4; j++) {
            float2 o2 = make_float2(s[2 * j] * r, s[2 * j + 1] * r);
            *reinterpret_cast<float2*>(dst + ((tk + (j << 3)) << 1)) = o2;
        }
    }
}

// ============================================================================
// asum[b,k] = sum_n a[b,n,k].  grid = B, 256 threads (coalesced over k).
// ============================================================================
__global__ __launch_bounds__(256) void asumK() {
    const int b  = blockIdx.x;
    const int k  = threadIdx.x & 63;
    const int sl = threadIdx.x >> 6;
    const float* ab = g_a + (size_t)b * NN * KK;
    float s = 0.f;
    for (int n = sl; n < NN; n += 4) s += ab[(size_t)n * KK + k];
    __shared__ float red[256];
    red[threadIdx.x] = s;
    __syncthreads();
    if (threadIdx.x < 64)
        g_asum[b * KK + threadIdx.x] =
            red[threadIdx.x] + red[threadIdx.x + 64] + red[threadIdx.x + 128] + red[threadIdx.x + 192];
}

// ============================================================================
// Phase B: vkd[b,k,d] = sum_n a[b,n,k] * x[b,n,d]
// grid = B*4 (d-blocks of 128), 256 threads.
// Thread layout: tk = warp id (k base = tk*8), td = lane (d = td + 32*i)
// Accumulators packed over k-pairs: acc[kp][i] <-> k = tk*8 + 2*kp (+1), d = td+32i
// ============================================================================
__global__ __launch_bounds__(256) void phaseB(const float* __restrict__ x) {
    __shared__ float as_[32][72];    // a chunk [32 n x 64 k], stride 72 (16B aligned)
    __shared__ float xsb[32][128];   // x chunk [32 n x 128 d]

    const int b   = blockIdx.x >> 2;
    const int d0  = (blockIdx.x & 3) << 7;
    const int tid = threadIdx.x;
    const int tk  = tid >> 5;
    const int td  = tid & 31;

    u64 acc[4][4];
#pragma unroll
    for (int kp = 0; kp < 4; kp++)
#pragma unroll
        for (int i = 0; i < 4; i++) acc[kp][i] = 0ull;

    const int ar = tid >> 3;          // 0..31
    const int ac = (tid & 7) << 3;    // 0..56 step 8
    const int xc = (tid & 7) << 4;    // 0..112 step 16

    const float* xb = x + (size_t)b * NN * DD + d0;
    const float* ab = g_a + (size_t)b * NN * KK;

    for (int nc = 0; nc < NN; nc += 32) {
        const float4* asrc = reinterpret_cast<const float4*>(ab + (size_t)(nc + ar) * KK + ac);
        float4 a0 = asrc[0], a1 = asrc[1];
        *reinterpret_cast<float4*>(&as_[ar][ac])     = a0;
        *reinterpret_cast<float4*>(&as_[ar][ac + 4]) = a1;

        const float4* xsrc = reinterpret_cast<const float4*>(xb + (size_t)(nc + ar) * DD + xc);
#pragma unroll
        for (int q = 0; q < 4; q++)
            *reinterpret_cast<float4*>(&xsb[ar][xc + (q << 2)]) = xsrc[q];
        __syncthreads();

#pragma unroll 4
        for (int n = 0; n < 32; n++) {
            u64 av[4];
#pragma unroll
            for (int kp = 0; kp < 4; kp++)
                av[kp] = *reinterpret_cast<const u64*>(&as_[n][(tk << 3) + (kp << 1)]);
            u64 xp[4];
#pragma unroll
            for (int i = 0; i < 4; i++) {
                float xv = xsb[n][td + (i << 5)];
                xp[i] = pack2(xv, xv);
            }
#pragma unroll
            for (int kp = 0; kp < 4; kp++)
#pragma unroll
                for (int i = 0; i < 4; i++) ffma2(acc[kp][i], av[kp], xp[i]);
        }
        __syncthreads();
    }

    float* vb = g_vkd + ((size_t)b * KK + (tk << 3)) * DD + d0;
#pragma unroll
    for (int kp = 0; kp < 4; kp++) {
#pragma unroll
        for (int i = 0; i < 4; i++) {
            float lo, hi;
            unpack2(acc[kp][i], lo, hi);
            vb[(size_t)(2 * kp) * DD + td + (i << 5)]     = lo;
            vb[(size_t)(2 * kp + 1) * DD + td + (i << 5)] = hi;
        }
    }
}

// ============================================================================
// Phase C-A: y = vkd + asum*C[:,k]; S_k = sum_d y^2; store y, S.
// grid = B*K = 4096, 128 threads.
// ============================================================================
__global__ __launch_bounds__(128) void phaseCA(const float* __restrict__ C) {
    const int b = blockIdx.x >> 6;
    const int k = blockIdx.x & 63;
    const float as = g_asum[b * KK + k];
    float* y = g_vkd + ((size_t)b * KK + k) * DD;
    const int tid = threadIdx.x;
    float ss = 0.f;
#pragma unroll
    for (int d = tid; d < DD; d += 128) {
        float v = y[d] + as * C[(size_t)d * KK + k];
        y[d] = v;
        ss += v * v;
    }
#pragma unroll
    for (int o = 16; o > 0; o >>= 1) ss += __shfl_xor_sync(0xffffffffu, ss, o);
    __shared__ float r4[4];
    if ((tid & 31) == 0) r4[tid >> 5] = ss;
    __syncthreads();
    if (tid == 0) g_S[b * KK + k] = r4[0] + r4[1] + r4[2] + r4[3];
}

// ============================================================================
// Phase C-B: intra-norm + transpose + global norm.
// out[b, d*K + k] = y[b,k,d] / sqrt(S_k+eps) / sqrt(G_b+eps),
//   G_b = sum_k S_k/(S_k+eps)
// grid = B, 256 threads.
// ============================================================================
__global__ __launch_bounds__(256) void phaseCB(float* __restrict__ out) {
    const int b   = blockIdx.x;
    const int tid = threadIdx.x;
    __shared__ float inv[64];
    __shared__ float gpart[64];
    __shared__ float gsh;
    if (tid < 64) {
        float s  = g_S[b * KK + tid];
        float iv = rsqrtf(s + FEPS);
        inv[tid]   = iv;
        gpart[tid] = s * iv * iv;   // = s/(s+eps)
    }
    __syncthreads();
    if (tid == 0) {
        float G = 0.f;
        for (int k = 0; k < 64; k++) G += gpart[k];
        gsh = rsqrtf(G + FEPS);
    }
    __syncthreads();
    const float gi = gsh;
    const float* y = g_vkd + (size_t)b * KK * DD;
    float* ob = out + (size_t)b * DD * KK;
    for (int idx = tid; idx < DD * KK; idx += 256) {
        int d = idx >> 6, k = idx & 63;
        ob[idx] = y[(size_t)k * DD + d] * inv[k] * gi;
    }
}

// ============================================================================
extern "C" void kernel_launch(void* const* d_in, const int* in_sizes, int n_in,
                              void* d_out, int out_size) {
    const float* x = (const float*)d_in[0];
    const float* w = (const float*)d_in[1];
    const float* C = (const float*)d_in[2];
    float* out = (float*)d_out;

    phaseA<<<BB * NN / 128, 256>>>(x, w);
    asumK<<<BB, 256>>>();
    phaseB<<<BB * 4, 256>>>(x);
    phaseCA<<<BB * KK, 128>>>(C);
    phaseCB<<<BB, 256>>>(out);
}

// round 2
// speedup vs baseline: 1.0006x; 1.0006x over previous
#include <cuda_runtime.h>

#define BB 64
#define NN 1024
#define DD 512
#define KK 64
#define FEPS 1e-12f

// ---------------- scratch (device globals; no allocation in kernel_launch) ---
__device__ float g_a[BB * NN * KK];      // softmax assignments [B,N,K]  (16.8 MB)
__device__ float g_vkd[BB * KK * DD];    // VLAD accumulator   [B,K,D]  ( 8.4 MB)
__device__ float g_asum[BB * KK];        // sum_n a[b,n,k]
__device__ float g_S[BB * KK];           // per-(b,k) sum of squares

typedef unsigned long long u64;

// ---------------- packed f32x2 helpers (sm_103a) ----------------------------
__device__ __forceinline__ u64 pack2(float lo, float hi) {
    u64 r;
    asm("mov.b64 %0, {%1, %2};" : "=l"(r) : "r"(__float_as_int(lo)), "r"(__float_as_int(hi)));
    return r;
}
__device__ __forceinline__ void unpack2(u64 v, float &lo, float &hi) {
    int a, b;
    asm("mov.b64 {%0, %1}, %2;" : "=r"(a), "=r"(b) : "l"(v));
    lo = __int_as_float(a);
    hi = __int_as_float(b);
}
__device__ __forceinline__ void ffma2(u64 &d, u64 a, u64 b) {
    asm("fma.rn.f32x2 %0, %1, %2, %0;" : "+l"(d) : "l"(a), "l"(b));
}

// ============================================================================
// Phase A: s = x @ w  (per 128-pixel tile), softmax over K=64, store a.
// grid = B*N/128 = 512 CTAs, 256 threads.
// Thread layout: tk = tid&7 (k-groups, interleaved pairs), tn = tid>>3 (pixels)
// Thread owns 4 pixels (tn, tn+32, tn+64, tn+96) x 8 k-values
// k mapping: pair j of thread tk -> k = 2*(tk + 8*j), 2*(tk+8*j)+1
// ============================================================================
__global__ __launch_bounds__(256) void phaseA(const float* __restrict__ x,
                                              const float* __restrict__ w) {
    __shared__ float xs[128][20];   // 128 pixels x 16 d, stride 20 (16B-aligned rows, no bank conflicts)
    __shared__ float ws[16][64];    // 16 d x 64 k

    const int blk = blockIdx.x;
    const int b   = blk >> 3;
    const int n0  = (blk & 7) << 7;
    const int tid = threadIdx.x;
    const int tk  = tid & 7;
    const int tn  = tid >> 3;

    u64 acc[4][4];
#pragma unroll
    for (int i = 0; i < 4; i++)
#pragma unroll
        for (int j = 0; j < 4; j++) acc[i][j] = 0ull;

    const float* xb = x + ((size_t)(b * NN + n0)) * DD;

    const int lr = tid >> 1;          // 0..127 pixel row for x staging
    const int lc = (tid & 1) << 3;    // 0 or 8
    const int wd = tid >> 4;          // 0..15 d row for w staging
    const int wk = (tid & 15) << 2;   // 0..60 step 4

    for (int dc = 0; dc < DD; dc += 16) {
        // stage x tile [128 x 16]
        float4 v0 = *reinterpret_cast<const float4*>(xb + (size_t)lr * DD + dc + lc);
        float4 v1 = *reinterpret_cast<const float4*>(xb + (size_t)lr * DD + dc + lc + 4);
        *reinterpret_cast<float4*>(&xs[lr][lc])     = v0;
        *reinterpret_cast<float4*>(&xs[lr][lc + 4]) = v1;
        // stage w tile [16 x 64]
        float4 wv4 = *reinterpret_cast<const float4*>(w + (size_t)(dc + wd) * KK + wk);
        *reinterpret_cast<float4*>(&ws[wd][wk]) = wv4;
        __syncthreads();

#pragma unroll
        for (int d = 0; d < 16; d++) {
            u64 xp[4];
#pragma unroll
            for (int i = 0; i < 4; i++) {
                float xv = xs[tn + (i << 5)][d];
                xp[i] = pack2(xv, xv);
            }
            u64 wv[4];
#pragma unroll
            for (int j = 0; j < 4; j++)
                wv[j] = *reinterpret_cast<const u64*>(&ws[d][(tk + (j << 3)) << 1]);
#pragma unroll
            for (int i = 0; i < 4; i++)
#pragma unroll
                for (int j = 0; j < 4; j++) ffma2(acc[i][j], xp[i], wv[j]);
        }
        __syncthreads();
    }

    // softmax over K=64: each pixel's 64 logits live in 8 consecutive lanes (tk 0..7)
#pragma unroll
    for (int i = 0; i < 4; i++) {
        float s[8];
#pragma unroll
        for (int j = 0; j < 4; j++) unpack2(acc[i][j], s[2 * j], s[2 * j + 1]);
        float m = s[0];
#pragma unroll
        for (int kk = 1; kk < 8; kk++) m = fmaxf(m, s[kk]);
#pragma unroll
        for (int o = 1; o < 8; o <<= 1) m = fmaxf(m, __shfl_xor_sync(0xffffffffu, m, o));
        float sum = 0.f;
#pragma unroll
        for (int kk = 0; kk < 8; kk++) { s[kk] = __expf(s[kk] - m); sum += s[kk]; }
#pragma unroll
        for (int o = 1; o < 8; o <<= 1) sum += __shfl_xor_sync(0xffffffffu, sum, o);
        const float r = 1.0f / sum;

        float* dst = g_a + ((size_t)(b * NN + n0 + tn + (i << 5))) * KK;
#pragma unroll
        for (int j = 0; j < 4; j++) {
            float2 o2 = make_float2(s[2 * j] * r, s[2 * j + 1] * r);
            *reinterpret_cast<float2*>(dst + ((tk + (j << 3)) << 1)) = o2;
        }
    }
}

// ============================================================================
// asum[b,k] = sum_n a[b,n,k].  grid = B, 256 threads (coalesced over k).
// ============================================================================
__global__ __launch_bounds__(256) void asumK() {
    const int b  = blockIdx.x;
    const int k  = threadIdx.x & 63;
    const int sl = threadIdx.x >> 6;
    const float* ab = g_a + (size_t)b * NN * KK;
    float s = 0.f;
    for (int n = sl; n < NN; n += 4) s += ab[(size_t)n * KK + k];
    __shared__ float red[256];
    red[threadIdx.x] = s;
    __syncthreads();
    if (threadIdx.x < 64)
        g_asum[b * KK + threadIdx.x] =
            red[threadIdx.x] + red[threadIdx.x + 64] + red[threadIdx.x + 128] + red[threadIdx.x + 192];
}

// ============================================================================
// Phase B: vkd[b,k,d] = sum_n a[b,n,k] * x[b,n,d]
// grid = B*4 (d-blocks of 128), 256 threads.
// Thread layout: tk = warp id (k base = tk*8), td = lane (d = td + 32*i)
// Accumulators packed over k-pairs: acc[kp][i] <-> k = tk*8 + 2*kp (+1), d = td+32i
// ============================================================================
__global__ __launch_bounds__(256) void phaseB(const float* __restrict__ x) {
    __shared__ float as_[32][72];    // a chunk [32 n x 64 k], stride 72 (16B aligned)
    __shared__ float xsb[32][128];   // x chunk [32 n x 128 d]

    const int b   = blockIdx.x >> 2;
    const int d0  = (blockIdx.x & 3) << 7;
    const int tid = threadIdx.x;
    const int tk  = tid >> 5;
    const int td  = tid & 31;

    u64 acc[4][4];
#pragma unroll
    for (int kp = 0; kp < 4; kp++)
#pragma unroll
        for (int i = 0; i < 4; i++) acc[kp][i] = 0ull;

    const int ar = tid >> 3;          // 0..31
    const int ac = (tid & 7) << 3;    // 0..56 step 8
    const int xc = (tid & 7) << 4;    // 0..112 step 16

    const float* xb = x + (size_t)b * NN * DD + d0;
    const float* ab = g_a + (size_t)b * NN * KK;

    for (int nc = 0; nc < NN; nc += 32) {
        const float4* asrc = reinterpret_cast<const float4*>(ab + (size_t)(nc + ar) * KK + ac);
        float4 a0 = asrc[0], a1 = asrc[1];
        *reinterpret_cast<float4*>(&as_[ar][ac])     = a0;
        *reinterpret_cast<float4*>(&as_[ar][ac + 4]) = a1;

        const float4* xsrc = reinterpret_cast<const float4*>(xb + (size_t)(nc + ar) * DD + xc);
#pragma unroll
        for (int q = 0; q < 4; q++)
            *reinterpret_cast<float4*>(&xsb[ar][xc + (q << 2)]) = xsrc[q];
        __syncthreads();

#pragma unroll 4
        for (int n = 0; n < 32; n++) {
            u64 av[4];
#pragma unroll
            for (int kp = 0; kp < 4; kp++)
                av[kp] = *reinterpret_cast<const u64*>(&as_[n][(tk << 3) + (kp << 1)]);
            u64 xp[4];
#pragma unroll
            for (int i = 0; i < 4; i++) {
                float xv = xsb[n][td + (i << 5)];
                xp[i] = pack2(xv, xv);
            }
#pragma unroll
            for (int kp = 0; kp < 4; kp++)
#pragma unroll
                for (int i = 0; i < 4; i++) ffma2(acc[kp][i], av[kp], xp[i]);
        }
        __syncthreads();
    }

    float* vb = g_vkd + ((size_t)b * KK + (tk << 3)) * DD + d0;
#pragma unroll
    for (int kp = 0; kp < 4; kp++) {
#pragma unroll
        for (int i = 0; i < 4; i++) {
            float lo, hi;
            unpack2(acc[kp][i], lo, hi);
            vb[(size_t)(2 * kp) * DD + td + (i << 5)]     = lo;
            vb[(size_t)(2 * kp + 1) * DD + td + (i << 5)] = hi;
        }
    }
}

// ============================================================================
// Phase C-A: y = vkd + asum*C[:,k]; S_k = sum_d y^2; store y, S.
// grid = B*K = 4096, 128 threads.
// ============================================================================
__global__ __launch_bounds__(128) void phaseCA(const float* __restrict__ C) {
    const int b = blockIdx.x >> 6;
    const int k = blockIdx.x & 63;
    const float as = g_asum[b * KK + k];
    float* y = g_vkd + ((size_t)b * KK + k) * DD;
    const int tid = threadIdx.x;
    float ss = 0.f;
#pragma unroll
    for (int d = tid; d < DD; d += 128) {
        float v = y[d] + as * C[(size_t)d * KK + k];
        y[d] = v;
        ss += v * v;
    }
#pragma unroll
    for (int o = 16; o > 0; o >>= 1) ss += __shfl_xor_sync(0xffffffffu, ss, o);
    __shared__ float r4[4];
    if ((tid & 31) == 0) r4[tid >> 5] = ss;
    __syncthreads();
    if (tid == 0) g_S[b * KK + k] = r4[0] + r4[1] + r4[2] + r4[3];
}

// ============================================================================
// Phase C-B: intra-norm + transpose + global norm.
// out[b, d*K + k] = y[b,k,d] / sqrt(S_k+eps) / sqrt(G_b+eps),
//   G_b = sum_k S_k/(S_k+eps)
// grid = B, 256 threads.
// ============================================================================
__global__ __launch_bounds__(256) void phaseCB(float* __restrict__ out) {
    const int b   = blockIdx.x;
    const int tid = threadIdx.x;
    __shared__ float inv[64];
    __shared__ float gpart[64];
    __shared__ float gsh;
    if (tid < 64) {
        float s  = g_S[b * KK + tid];
        float iv = rsqrtf(s + FEPS);
        inv[tid]   = iv;
        gpart[tid] = s * iv * iv;   // = s/(s+eps)
    }
    __syncthreads();
    if (tid == 0) {
        float G = 0.f;
        for (int k = 0; k < 64; k++) G += gpart[k];
        gsh = rsqrtf(G + FEPS);
    }
    __syncthreads();
    const float gi = gsh;
    const float* y = g_vkd + (size_t)b * KK * DD;
    float* ob = out + (size_t)b * DD * KK;
    for (int idx = tid; idx < DD * KK; idx += 256) {
        int d = idx >> 6, k = idx & 63;
        ob[idx] = y[(size_t)k * DD + d] * inv[k] * gi;
    }
}

// ============================================================================
extern "C" void kernel_launch(void* const* d_in, const int* in_sizes, int n_in,
                              void* d_out, int out_size) {
    const float* x = (const float*)d_in[0];
    const float* w = (const float*)d_in[1];
    const float* C = (const float*)d_in[2];
    float* out = (float*)d_out;

    phaseA<<<BB * NN / 128, 256>>>(x, w);
    asumK<<<BB, 256>>>();
    phaseB<<<BB * 4, 256>>>(x);
    phaseCA<<<BB * KK, 128>>>(C);
    phaseCB<<<BB, 256>>>(out);
}